// round 2
// baseline (speedup 1.0000x reference)
#include <cuda_runtime.h>
#include <math.h>

// Problem constants
#define NB   64        // batch
#define TT   200       // timesteps
#define DIN  512
#define HID  1024
#define DOUT 512
#define DELAYN 20      // synaptic delay steps
#define NBLK (TT / DELAYN)   // 10 blocks of 20 steps

// Persistent scratch (device globals — no allocation allowed)
__device__ float g_xp [NB * TT * HID];        // x @ W_in, layout [B,T,H], row = b*TT+t
__device__ float g_fir[TT * NB * HID];        // firing, layout [T,B,H], row = t*NB+b
__device__ float g_lat[DELAYN * NB * HID];    // lateral contribution for current block, row = s*NB+b
__device__ float g_volt[NB * HID];
__device__ float g_asc [2 * NB * HID];

// ---------------------------------------------------------------------------
// SGEMM: 128x128 block tile, BK=8, 256 threads, 8x8 microtile.
// TRANSB: B matrix is [N,K] row-major (use B^T)
// REMAP : output row r = t*NB+b is written to C[((b*TT+t)*DOUT)] (out gemm)
// BIAS  : add bias[col]
// Requires M%128==0, N%128==0, K%8==0 (holds for all our shapes).
// ---------------------------------------------------------------------------
template<int TRANSB, int REMAP, int BIAS>
__global__ __launch_bounds__(256, 2)
void sgemm_kernel(const float* __restrict__ A, const float* __restrict__ B,
                  float* __restrict__ C, const float* __restrict__ bias,
                  int M, int N, int K)
{
    __shared__ float As[8][132];   // pad 132 -> conflict-free transposed stores
    __shared__ float Bs[8][132];

    const int tid = threadIdx.x;
    const int bm = blockIdx.y * 128;
    const int bn = blockIdx.x * 128;

    // A (and transposed-B) load mapping: 1 float4 along K per thread
    const int ar = tid >> 1;          // 0..127 row within tile
    const int ak = (tid & 1) * 4;     // 0 or 4  k-offset

    // NN B load mapping: 1 float4 along N per thread
    const int br = tid >> 5;          // 0..7   k row
    const int bc = (tid & 31) * 4;    // 0..124 n col

    const int tx = tid & 15;          // col group
    const int ty = tid >> 4;          // row group

    float acc[8][8];
    #pragma unroll
    for (int i = 0; i < 8; ++i)
        #pragma unroll
        for (int j = 0; j < 8; ++j) acc[i][j] = 0.0f;

    for (int k0 = 0; k0 < K; k0 += 8) {
        // --- load A tile (transpose into smem) ---
        float4 av = *reinterpret_cast<const float4*>(&A[(size_t)(bm + ar) * K + k0 + ak]);
        As[ak + 0][ar] = av.x;
        As[ak + 1][ar] = av.y;
        As[ak + 2][ar] = av.z;
        As[ak + 3][ar] = av.w;

        // --- load B tile ---
        if (TRANSB) {
            float4 bv = *reinterpret_cast<const float4*>(&B[(size_t)(bn + ar) * K + k0 + ak]);
            Bs[ak + 0][ar] = bv.x;
            Bs[ak + 1][ar] = bv.y;
            Bs[ak + 2][ar] = bv.z;
            Bs[ak + 3][ar] = bv.w;
        } else {
            float4 bv = *reinterpret_cast<const float4*>(&B[(size_t)(k0 + br) * N + bn + bc]);
            *reinterpret_cast<float4*>(&Bs[br][bc]) = bv;
        }
        __syncthreads();

        #pragma unroll
        for (int kk = 0; kk < 8; ++kk) {
            float a[8], bf[8];
            *reinterpret_cast<float4*>(&a[0])  = *reinterpret_cast<const float4*>(&As[kk][ty * 8]);
            *reinterpret_cast<float4*>(&a[4])  = *reinterpret_cast<const float4*>(&As[kk][ty * 8 + 4]);
            *reinterpret_cast<float4*>(&bf[0]) = *reinterpret_cast<const float4*>(&Bs[kk][tx * 8]);
            *reinterpret_cast<float4*>(&bf[4]) = *reinterpret_cast<const float4*>(&Bs[kk][tx * 8 + 4]);
            #pragma unroll
            for (int i = 0; i < 8; ++i)
                #pragma unroll
                for (int j = 0; j < 8; ++j)
                    acc[i][j] += a[i] * bf[j];
        }
        __syncthreads();
    }

    // --- epilogue ---
    #pragma unroll
    for (int i = 0; i < 8; ++i) {
        int row = bm + ty * 8 + i;
        float* crow;
        if (REMAP) {
            int t = row >> 6;         // row = t*NB + b, NB = 64
            int b = row & 63;
            crow = C + (size_t)(b * TT + t) * DOUT;
        } else {
            crow = C + (size_t)row * N;
        }
        #pragma unroll
        for (int j = 0; j < 8; j += 4) {
            int col = bn + tx * 8 + j;
            float4 v;
            v.x = acc[i][j + 0];
            v.y = acc[i][j + 1];
            v.z = acc[i][j + 2];
            v.w = acc[i][j + 3];
            if (BIAS) {
                v.x += bias[col + 0];
                v.y += bias[col + 1];
                v.z += bias[col + 2];
                v.w += bias[col + 3];
            }
            *reinterpret_cast<float4*>(&crow[col]) = v;
        }
    }
}

// ---------------------------------------------------------------------------
// Elementwise recurrence over one block of DELAYN=20 steps.
// Each thread owns one (b,h); the 20-step loop runs in registers.
// For k0step==0 the carry initializes to zero (matches reference carry0),
// so no separate state-reset kernel is needed (deterministic per launch).
// ---------------------------------------------------------------------------
__global__ __launch_bounds__(256)
void step_block(int k0step, int useLat,
                const float* __restrict__ thresh,
                const float* __restrict__ tkm,
                const float* __restrict__ tak,
                const float* __restrict__ amp,
                const float* __restrict__ tar)
{
    const int idx = blockIdx.x * blockDim.x + threadIdx.x;   // 0 .. NB*HID-1
    const int h = idx & (HID - 1);
    const int b = idx >> 10;

    const float th  = thresh[h];
    const float km  = 1.0f / (1.0f + expf(-tkm[h]));          // DT * k_m = sigmoid(trans_k_m)
    const float rk  = 0.1f * km;                              // R_MEM * DT * k_m
    const float omk = 1.0f - km;

    const float dk0 = 1.0f / (1.0f + expf(-tak[h]));          // DT * k_asc[0]
    const float dk1 = 1.0f / (1.0f + expf(-tak[HID + h]));
    const float am0 = amp[h];
    const float am1 = amp[HID + h];
    const float r0  = 1.0f - 2.0f / (1.0f + expf(-tar[h]));
    const float r1  = 1.0f - 2.0f / (1.0f + expf(-tar[HID + h]));

    float v, a0, a1, fp;
    if (k0step == 0) {
        v = 0.0f; a0 = 0.0f; a1 = 0.0f; fp = 0.0f;
    } else {
        v  = g_volt[idx];
        a0 = g_asc[idx];
        a1 = g_asc[NB * HID + idx];
        fp = g_fir[(size_t)(k0step - 1) * NB * HID + (size_t)b * HID + h];
    }

    #pragma unroll
    for (int s = 0; s < DELAYN; ++s) {
        const int t = k0step + s;
        float syn = g_xp[((size_t)b * TT + t) * HID + h];
        if (useLat) syn += g_lat[((size_t)s * NB + b) * HID + h];

        // after-spike currents (use previous-step firing fp)
        a0 = (am0 + r0 * a0) * fp * dk0 + (1.0f - dk0) * a0;
        a1 = (am1 + r1 * a1) * fp * dk1 + (1.0f - dk1) * a1;

        // membrane voltage (V_RESET = 0)
        v = rk * (syn + a0 + a1) + omk * v;

        // smoothed spike
        fp = 1.0f / (1.0f + expf(-(v - th)));
        g_fir[((size_t)t * NB + b) * HID + h] = fp;
    }

    g_volt[idx] = v;
    g_asc[idx] = a0;
    g_asc[NB * HID + idx] = a1;
}

extern "C" void kernel_launch(void* const* d_in, const int* in_sizes, int n_in,
                              void* d_out, int out_size)
{
    const float* x      = (const float*)d_in[0];   // [B,T,IN]
    const float* W_in   = (const float*)d_in[1];   // [IN,HID]
    const float* W_lat  = (const float*)d_in[2];   // [HID,HID]
    const float* thresh = (const float*)d_in[3];   // [1,HID]
    const float* tkm    = (const float*)d_in[4];   // [1,HID]
    const float* tak    = (const float*)d_in[5];   // [2,1,HID]
    const float* amp    = (const float*)d_in[6];   // [2,1,HID]
    const float* tar    = (const float*)d_in[7];   // [2,1,HID]
    const float* W_out  = (const float*)d_in[8];   // [OUT,HID]
    const float* b_out  = (const float*)d_in[9];   // [OUT]
    float* out = (float*)d_out;                    // [B,T,OUT]

    float *xp, *fir, *lat;
    cudaGetSymbolAddress((void**)&xp,  g_xp);
    cudaGetSymbolAddress((void**)&fir, g_fir);
    cudaGetSymbolAddress((void**)&lat, g_lat);

    // 1) Input projection: [B*T, IN] @ [IN, HID] -> g_xp   (M=12800, N=1024, K=512)
    sgemm_kernel<0, 0, 0><<<dim3(HID / 128, (NB * TT) / 128), 256>>>(
        x, W_in, xp, nullptr, NB * TT, HID, DIN);

    // 2) Ten blocks of 20 steps: lateral GEMM (delayed firing) + elementwise recurrence
    for (int k = 0; k < NBLK; ++k) {
        if (k > 0) {
            // firing[(k-1)*20 .. k*20-1] @ W_lat : [1280,1024] @ [1024,1024]
            sgemm_kernel<0, 0, 0><<<dim3(HID / 128, (DELAYN * NB) / 128), 256>>>(
                fir + (size_t)(k - 1) * DELAYN * NB * HID, W_lat, lat, nullptr,
                DELAYN * NB, HID, HID);
        }
        step_block<<<(NB * HID) / 256, 256>>>(k * DELAYN, k > 0, thresh, tkm, tak, amp, tar);
    }

    // 3) Readout: firing [12800,1024] @ W_out^T [1024,512] + bias, remapped to [B,T,OUT]
    sgemm_kernel<1, 1, 1><<<dim3(DOUT / 128, (NB * TT) / 128), 256>>>(
        fir, W_out, out, b_out, NB * TT, DOUT, HID);
}

// round 7
// speedup vs baseline: 2.5162x; 2.5162x over previous
#include <cuda_runtime.h>
#include <math.h>
#include <stdint.h>

// Problem constants
#define NB   64
#define TT   200
#define DIN  512
#define HID  1024
#define DOUT 512
#define DELAYN 20
#define NBLK 10

// Persistent scratch (device globals — no allocation allowed)
__device__ __align__(16) float g_xp [NB * TT * HID];       // x @ W_in, [B,T,H]
__device__ __align__(16) float g_fir[TT * NB * HID];       // firing, [T,B,H]
__device__ __align__(16) float g_lat[DELAYN * NB * HID];   // lateral contrib, [s,B,H]
__device__ __align__(16) float g_volt[NB * HID];
__device__ __align__(16) float g_asc [2 * NB * HID];
__device__ __align__(16) float g_WoutT[HID * DOUT];        // W_out transposed [HID,DOUT]

// ---------------------------------------------------------------------------
// TF32 tensor-core GEMM: 128x128 tile, BK=16, 256 threads, double-buffered
// cp.async. Warp grid 2(m)x4(n), each warp 64x32 via m16n8k8 MMAs.
// Requires M%128==0, N%128==0, K%16==0 (true for all shapes here).
// REMAP: output row r = t*NB+b written to C[(b*TT+t)*N]   (final readout)
// BIAS : add bias[col]
// ---------------------------------------------------------------------------
#define BM 128
#define BN 128
#define BKT 16
#define ASTR 20    // BK + 4  -> A-frag LDS conflict-free (bank = 20m+k)
#define BSTR 136   // BN + 8  -> B-frag LDS conflict-free (bank = 8k+n)
#define A_STAGE_BYTES (BM * ASTR * 4)
#define B_STAGE_BYTES (BKT * BSTR * 4)

__device__ __forceinline__ uint32_t cvt_tf32(float x) {
    uint32_t u;
    asm("cvt.rna.tf32.f32 %0, %1;" : "=r"(u) : "f"(x));
    return u;
}

__device__ __forceinline__ void cp16(uint32_t dst, const float* src) {
    asm volatile("cp.async.cg.shared.global [%0], [%1], 16;\n" :: "r"(dst), "l"(src));
}

__device__ __forceinline__ void mma8(float* c, const uint32_t* a, const uint32_t* b) {
    asm volatile(
        "mma.sync.aligned.m16n8k8.row.col.f32.tf32.tf32.f32 "
        "{%0,%1,%2,%3}, {%4,%5,%6,%7}, {%8,%9}, {%0,%1,%2,%3};\n"
        : "+f"(c[0]), "+f"(c[1]), "+f"(c[2]), "+f"(c[3])
        : "r"(a[0]), "r"(a[1]), "r"(a[2]), "r"(a[3]), "r"(b[0]), "r"(b[1]));
}

template<int REMAP, int BIAS>
__global__ __launch_bounds__(256, 2)
void gemm_tf32(const float* __restrict__ A, const float* __restrict__ B,
               float* __restrict__ C, const float* __restrict__ bias,
               int M, int N, int K)
{
    __shared__ float As[2][BM * ASTR];
    __shared__ float Bs[2][BKT * BSTR];

    const int tid  = threadIdx.x;
    const int wid  = tid >> 5;
    const int lane = tid & 31;
    const int grp  = lane >> 2;      // 0..7
    const int tig  = lane & 3;       // 0..3
    const int wm   = (wid & 1) * 64; // warp m-offset
    const int wn   = (wid >> 1) * 32;// warp n-offset
    const int bm   = blockIdx.y * BM;
    const int bn   = blockIdx.x * BN;

    const uint32_t sA = (uint32_t)__cvta_generic_to_shared(&As[0][0]);
    const uint32_t sB = (uint32_t)__cvta_generic_to_shared(&Bs[0][0]);

    // global->smem load coords: each thread 2 float4 of A, 2 float4 of B
    const int a_r = tid >> 1;             // 0..127
    const int a_k = (tid & 1) * 8;        // 0 or 8
    const int b_r = tid >> 4;             // 0..15
    const int b_n = (tid & 15) * 8;       // 0..120

    float acc[4][4][4];
    #pragma unroll
    for (int mi = 0; mi < 4; ++mi)
        #pragma unroll
        for (int ni = 0; ni < 4; ++ni)
            #pragma unroll
            for (int j = 0; j < 4; ++j) acc[mi][ni][j] = 0.0f;

    const int ktiles = K / BKT;

    // prefetch stage 0
    {
        const float* Ag = &A[(size_t)(bm + a_r) * K + a_k];
        cp16(sA + (uint32_t)((a_r * ASTR + a_k) * 4), Ag);
        cp16(sA + (uint32_t)((a_r * ASTR + a_k + 4) * 4), Ag + 4);
        const float* Bg = &B[(size_t)b_r * N + bn + b_n];
        cp16(sB + (uint32_t)((b_r * BSTR + b_n) * 4), Bg);
        cp16(sB + (uint32_t)((b_r * BSTR + b_n + 4) * 4), Bg + 4);
        asm volatile("cp.async.commit_group;\n" ::: "memory");
    }

    for (int kt = 0; kt < ktiles; ++kt) {
        asm volatile("cp.async.wait_group 0;\n" ::: "memory");
        __syncthreads();

        if (kt + 1 < ktiles) {
            const int k0 = (kt + 1) * BKT;
            const uint32_t ab = sA + (uint32_t)(((kt + 1) & 1) * A_STAGE_BYTES);
            const uint32_t bb = sB + (uint32_t)(((kt + 1) & 1) * B_STAGE_BYTES);
            const float* Ag = &A[(size_t)(bm + a_r) * K + k0 + a_k];
            cp16(ab + (uint32_t)((a_r * ASTR + a_k) * 4), Ag);
            cp16(ab + (uint32_t)((a_r * ASTR + a_k + 4) * 4), Ag + 4);
            const float* Bg = &B[(size_t)(k0 + b_r) * N + bn + b_n];
            cp16(bb + (uint32_t)((b_r * BSTR + b_n) * 4), Bg);
            cp16(bb + (uint32_t)((b_r * BSTR + b_n + 4) * 4), Bg + 4);
            asm volatile("cp.async.commit_group;\n" ::: "memory");
        }

        const float* as = As[kt & 1];
        const float* bs = Bs[kt & 1];

        #pragma unroll
        for (int kc = 0; kc < 2; ++kc) {
            const int kb = kc * 8 + tig;

            uint32_t af[4][4];
            #pragma unroll
            for (int mi = 0; mi < 4; ++mi) {
                const float* p = &as[(wm + mi * 16 + grp) * ASTR + kb];
                af[mi][0] = cvt_tf32(p[0]);
                af[mi][1] = cvt_tf32(p[8 * ASTR]);
                af[mi][2] = cvt_tf32(p[4]);
                af[mi][3] = cvt_tf32(p[8 * ASTR + 4]);
            }
            uint32_t bf[4][2];
            #pragma unroll
            for (int ni = 0; ni < 4; ++ni) {
                const float* p = &bs[kb * BSTR + wn + ni * 8 + grp];
                bf[ni][0] = cvt_tf32(p[0]);
                bf[ni][1] = cvt_tf32(p[4 * BSTR]);
            }
            #pragma unroll
            for (int mi = 0; mi < 4; ++mi)
                #pragma unroll
                for (int ni = 0; ni < 4; ++ni)
                    mma8(acc[mi][ni], af[mi], bf[ni]);
        }
    }

    // epilogue
    #pragma unroll
    for (int mi = 0; mi < 4; ++mi) {
        const int r0 = bm + wm + mi * 16 + grp;
        const int r1 = r0 + 8;
        float *row0, *row1;
        if (REMAP) {
            row0 = C + (size_t)((r0 & 63) * TT + (r0 >> 6)) * N;
            row1 = C + (size_t)((r1 & 63) * TT + (r1 >> 6)) * N;
        } else {
            row0 = C + (size_t)r0 * N;
            row1 = C + (size_t)r1 * N;
        }
        #pragma unroll
        for (int ni = 0; ni < 4; ++ni) {
            const int col = bn + wn + ni * 8 + tig * 2;
            float2 v0 = make_float2(acc[mi][ni][0], acc[mi][ni][1]);
            float2 v1 = make_float2(acc[mi][ni][2], acc[mi][ni][3]);
            if (BIAS) {
                const float bx = bias[col], by = bias[col + 1];
                v0.x += bx; v0.y += by; v1.x += bx; v1.y += by;
            }
            *reinterpret_cast<float2*>(&row0[col]) = v0;
            *reinterpret_cast<float2*>(&row1[col]) = v1;
        }
    }
}

// ---------------------------------------------------------------------------
// W_out [DOUT, HID] -> g_WoutT [HID, DOUT]
// ---------------------------------------------------------------------------
__global__ void transpose_wout(const float* __restrict__ in, float* __restrict__ out)
{
    __shared__ float tile[32][33];
    const int bx = blockIdx.x * 32;   // HID coord
    const int by = blockIdx.y * 32;   // DOUT coord
    #pragma unroll
    for (int j = 0; j < 32; j += 8)
        tile[threadIdx.y + j][threadIdx.x] =
            in[(size_t)(by + threadIdx.y + j) * HID + bx + threadIdx.x];
    __syncthreads();
    #pragma unroll
    for (int j = 0; j < 32; j += 8)
        out[(size_t)(bx + threadIdx.y + j) * DOUT + by + threadIdx.x] =
            tile[threadIdx.x][threadIdx.y + j];
}

// ---------------------------------------------------------------------------
// Elementwise recurrence over DELAYN=20 steps; 4 hidden units per thread
// (float4 loads/stores for MLP). k0step==0 initializes carry to zero.
// ---------------------------------------------------------------------------
__global__ __launch_bounds__(64)
void step_block(int k0step, int useLat,
                const float* __restrict__ thresh,
                const float* __restrict__ tkm,
                const float* __restrict__ tak,
                const float* __restrict__ amp,
                const float* __restrict__ tar)
{
    const int idx = blockIdx.x * 64 + threadIdx.x;   // 0 .. NB*HID/4-1
    const int h = (idx & 255) * 4;                   // HID/4 = 256
    const int b = idx >> 8;
    const int base = b * HID + h;

    float th[4], rk[4], omk[4], dk0[4], dk1[4], odk0[4], odk1[4];
    float am0[4], am1[4], rr0[4], rr1[4];
    {
        float4 t = *reinterpret_cast<const float4*>(&thresh[h]);
        th[0] = t.x; th[1] = t.y; th[2] = t.z; th[3] = t.w;
        float4 m = *reinterpret_cast<const float4*>(&tkm[h]);
        float mm[4] = {m.x, m.y, m.z, m.w};
        float4 k0v = *reinterpret_cast<const float4*>(&tak[h]);
        float4 k1v = *reinterpret_cast<const float4*>(&tak[HID + h]);
        float kk0[4] = {k0v.x, k0v.y, k0v.z, k0v.w};
        float kk1[4] = {k1v.x, k1v.y, k1v.z, k1v.w};
        float4 a0v = *reinterpret_cast<const float4*>(&amp[h]);
        float4 a1v = *reinterpret_cast<const float4*>(&amp[HID + h]);
        am0[0] = a0v.x; am0[1] = a0v.y; am0[2] = a0v.z; am0[3] = a0v.w;
        am1[0] = a1v.x; am1[1] = a1v.y; am1[2] = a1v.z; am1[3] = a1v.w;
        float4 r0v = *reinterpret_cast<const float4*>(&tar[h]);
        float4 r1v = *reinterpret_cast<const float4*>(&tar[HID + h]);
        float rv0[4] = {r0v.x, r0v.y, r0v.z, r0v.w};
        float rv1[4] = {r1v.x, r1v.y, r1v.z, r1v.w};
        #pragma unroll
        for (int j = 0; j < 4; ++j) {
            const float km = 1.0f / (1.0f + expf(-mm[j]));     // DT*k_m
            rk[j]  = 0.1f * km;                                // R_MEM*DT*k_m
            omk[j] = 1.0f - km;
            dk0[j] = 1.0f / (1.0f + expf(-kk0[j]));
            dk1[j] = 1.0f / (1.0f + expf(-kk1[j]));
            odk0[j] = 1.0f - dk0[j];
            odk1[j] = 1.0f - dk1[j];
            rr0[j] = 1.0f - 2.0f / (1.0f + expf(-rv0[j]));
            rr1[j] = 1.0f - 2.0f / (1.0f + expf(-rv1[j]));
        }
    }

    float v[4], a0[4], a1[4], f[4];
    if (k0step == 0) {
        #pragma unroll
        for (int j = 0; j < 4; ++j) { v[j] = 0.f; a0[j] = 0.f; a1[j] = 0.f; f[j] = 0.f; }
    } else {
        float4 vv = *reinterpret_cast<const float4*>(&g_volt[base]);
        float4 aa0 = *reinterpret_cast<const float4*>(&g_asc[base]);
        float4 aa1 = *reinterpret_cast<const float4*>(&g_asc[NB * HID + base]);
        float4 ff = *reinterpret_cast<const float4*>(&g_fir[(size_t)(k0step - 1) * NB * HID + base]);
        v[0] = vv.x; v[1] = vv.y; v[2] = vv.z; v[3] = vv.w;
        a0[0] = aa0.x; a0[1] = aa0.y; a0[2] = aa0.z; a0[3] = aa0.w;
        a1[0] = aa1.x; a1[1] = aa1.y; a1[2] = aa1.z; a1[3] = aa1.w;
        f[0] = ff.x; f[1] = ff.y; f[2] = ff.z; f[3] = ff.w;
    }

    #pragma unroll
    for (int s = 0; s < DELAYN; ++s) {
        const int t = k0step + s;
        float4 syn = *reinterpret_cast<const float4*>(&g_xp[((size_t)b * TT + t) * HID + h]);
        float sy[4] = {syn.x, syn.y, syn.z, syn.w};
        if (useLat) {
            float4 l = *reinterpret_cast<const float4*>(&g_lat[((size_t)s * NB + b) * HID + h]);
            sy[0] += l.x; sy[1] += l.y; sy[2] += l.z; sy[3] += l.w;
        }
        #pragma unroll
        for (int j = 0; j < 4; ++j) {
            a0[j] = (am0[j] + rr0[j] * a0[j]) * f[j] * dk0[j] + odk0[j] * a0[j];
            a1[j] = (am1[j] + rr1[j] * a1[j]) * f[j] * dk1[j] + odk1[j] * a1[j];
            v[j]  = rk[j] * (sy[j] + a0[j] + a1[j]) + omk[j] * v[j];
            f[j]  = __fdividef(1.0f, 1.0f + __expf(-(v[j] - th[j])));
        }
        float4 o = make_float4(f[0], f[1], f[2], f[3]);
        *reinterpret_cast<float4*>(&g_fir[((size_t)t * NB + b) * HID + h]) = o;
    }

    *reinterpret_cast<float4*>(&g_volt[base]) = make_float4(v[0], v[1], v[2], v[3]);
    *reinterpret_cast<float4*>(&g_asc[base]) = make_float4(a0[0], a0[1], a0[2], a0[3]);
    *reinterpret_cast<float4*>(&g_asc[NB * HID + base]) = make_float4(a1[0], a1[1], a1[2], a1[3]);
}

extern "C" void kernel_launch(void* const* d_in, const int* in_sizes, int n_in,
                              void* d_out, int out_size)
{
    const float* x      = (const float*)d_in[0];
    const float* W_in   = (const float*)d_in[1];
    const float* W_lat  = (const float*)d_in[2];
    const float* thresh = (const float*)d_in[3];
    const float* tkm    = (const float*)d_in[4];
    const float* tak    = (const float*)d_in[5];
    const float* amp    = (const float*)d_in[6];
    const float* tar    = (const float*)d_in[7];
    const float* W_out  = (const float*)d_in[8];
    const float* b_out  = (const float*)d_in[9];
    float* out = (float*)d_out;

    float *xp, *fir, *lat, *woutT;
    cudaGetSymbolAddress((void**)&xp,  g_xp);
    cudaGetSymbolAddress((void**)&fir, g_fir);
    cudaGetSymbolAddress((void**)&lat, g_lat);
    cudaGetSymbolAddress((void**)&woutT, g_WoutT);

    // 0) Transpose W_out once (so readout GEMM is NN)
    transpose_wout<<<dim3(HID / 32, DOUT / 32), dim3(32, 8)>>>(W_out, woutT);

    // 1) Input projection: [12800,512] @ [512,1024] -> g_xp
    gemm_tf32<0, 0><<<dim3(HID / BN, (NB * TT) / BM), 256>>>(
        x, W_in, xp, nullptr, NB * TT, HID, DIN);

    // 2) Ten blocks of 20 steps: lateral GEMM + elementwise recurrence
    for (int k = 0; k < NBLK; ++k) {
        if (k > 0) {
            gemm_tf32<0, 0><<<dim3(HID / BN, (DELAYN * NB) / BM), 256>>>(
                fir + (size_t)(k - 1) * DELAYN * NB * HID, W_lat, lat, nullptr,
                DELAYN * NB, HID, HID);
        }
        step_block<<<(NB * HID / 4) / 64, 64>>>(k * DELAYN, k > 0, thresh, tkm, tak, amp, tar);
    }

    // 3) Readout: [12800,1024] @ [1024,512] + bias, remapped to [B,T,OUT]
    gemm_tf32<1, 1><<<dim3(DOUT / BN, (NB * TT) / BM), 256>>>(
        fir, woutT, out, b_out, NB * TT, DOUT, HID);
}

// round 9
// speedup vs baseline: 2.6283x; 1.0446x over previous
#include <cuda_runtime.h>
#include <math.h>
#include <stdint.h>

// Problem constants
#define NB   64
#define TT   200
#define DIN  512
#define HID  1024
#define DOUT 512
#define DELAYN 20
#define NBLK 10

// Persistent scratch (device globals — no allocation allowed)
__device__ __align__(16) float g_xp [NB * TT * HID];       // x @ W_in, [B,T,H]
__device__ __align__(16) float g_fir[TT * NB * HID];       // firing (tf32-rounded), [T,B,H]
__device__ __align__(16) float g_lat[DELAYN * NB * HID];   // lateral contrib, [s,B,H]
__device__ __align__(16) float g_volt[NB * HID];
__device__ __align__(16) float g_asc [2 * NB * HID];
__device__ __align__(16) float g_WoutT[HID * DOUT];        // W_out^T, tf32-rounded
__device__ __align__(16) float g_Wlat32[HID * HID];        // W_lat, tf32-rounded
__device__ __align__(16) float g_Win32[DIN * HID];         // W_in, tf32-rounded

__device__ __forceinline__ uint32_t cvt_tf32(float x) {
    uint32_t u;
    asm("cvt.rna.tf32.f32 %0, %1;" : "=r"(u) : "f"(x));
    return u;
}

__device__ __forceinline__ void cp16(uint32_t dst, const float* src) {
    asm volatile("cp.async.cg.shared.global [%0], [%1], 16;\n" :: "r"(dst), "l"(src));
}

__device__ __forceinline__ void mma8(float* c, const uint32_t* a, const uint32_t* b) {
    asm volatile(
        "mma.sync.aligned.m16n8k8.row.col.f32.tf32.tf32.f32 "
        "{%0,%1,%2,%3}, {%4,%5,%6,%7}, {%8,%9}, {%0,%1,%2,%3};\n"
        : "+f"(c[0]), "+f"(c[1]), "+f"(c[2]), "+f"(c[3])
        : "r"(a[0]), "r"(a[1]), "r"(a[2]), "r"(a[3]), "r"(b[0]), "r"(b[1]));
}

// ---------------------------------------------------------------------------
// Elementwise tf32 rounding: out[i] = tf32(in[i]) (float4 vectorized)
// ---------------------------------------------------------------------------
__global__ void round_tf32_kernel(const float* __restrict__ in, float* __restrict__ out, int n4)
{
    int i = blockIdx.x * blockDim.x + threadIdx.x;
    if (i >= n4) return;
    float4 v = reinterpret_cast<const float4*>(in)[i];
    v.x = __uint_as_float(cvt_tf32(v.x));
    v.y = __uint_as_float(cvt_tf32(v.y));
    v.z = __uint_as_float(cvt_tf32(v.z));
    v.w = __uint_as_float(cvt_tf32(v.w));
    reinterpret_cast<float4*>(out)[i] = v;
}

// ---------------------------------------------------------------------------
// Big TF32 GEMM: 128x128 tile, BK=16, 256 threads, double-buffered cp.async.
// Warp grid 2(m)x4(n), each warp 64x32. CVTA: round A fragments (A not
// pre-rounded). B must ALWAYS be pre-rounded to tf32.
// ---------------------------------------------------------------------------
#define BM 128
#define BN 128
#define BKT 16
#define ASTR 20    // BK + 4
#define BSTR 136   // BN + 8 (mod 32 == 8 -> conflict-free)
#define A_STAGE_BYTES (BM * ASTR * 4)
#define B_STAGE_BYTES (BKT * BSTR * 4)

template<int REMAP, int BIAS, int CVTA>
__global__ __launch_bounds__(256, 2)
void gemm_tf32(const float* __restrict__ A, const float* __restrict__ B,
               float* __restrict__ C, const float* __restrict__ bias,
               int M, int N, int K)
{
    __shared__ float As[2][BM * ASTR];
    __shared__ float Bs[2][BKT * BSTR];

    const int tid  = threadIdx.x;
    const int wid  = tid >> 5;
    const int lane = tid & 31;
    const int grp  = lane >> 2;
    const int tig  = lane & 3;
    const int wm   = (wid & 1) * 64;
    const int wn   = (wid >> 1) * 32;
    const int bm   = blockIdx.y * BM;
    const int bn   = blockIdx.x * BN;

    const uint32_t sA = (uint32_t)__cvta_generic_to_shared(&As[0][0]);
    const uint32_t sB = (uint32_t)__cvta_generic_to_shared(&Bs[0][0]);

    const int a_r = tid >> 1;
    const int a_k = (tid & 1) * 8;
    const int b_r = tid >> 4;
    const int b_n = (tid & 15) * 8;

    float acc[4][4][4];
    #pragma unroll
    for (int mi = 0; mi < 4; ++mi)
        #pragma unroll
        for (int ni = 0; ni < 4; ++ni)
            #pragma unroll
            for (int j = 0; j < 4; ++j) acc[mi][ni][j] = 0.0f;

    const int ktiles = K / BKT;

    {
        const float* Ag = &A[(size_t)(bm + a_r) * K + a_k];
        cp16(sA + (uint32_t)((a_r * ASTR + a_k) * 4), Ag);
        cp16(sA + (uint32_t)((a_r * ASTR + a_k + 4) * 4), Ag + 4);
        const float* Bg = &B[(size_t)b_r * N + bn + b_n];
        cp16(sB + (uint32_t)((b_r * BSTR + b_n) * 4), Bg);
        cp16(sB + (uint32_t)((b_r * BSTR + b_n + 4) * 4), Bg + 4);
        asm volatile("cp.async.commit_group;\n" ::: "memory");
    }

    for (int kt = 0; kt < ktiles; ++kt) {
        asm volatile("cp.async.wait_group 0;\n" ::: "memory");
        __syncthreads();

        if (kt + 1 < ktiles) {
            const int k0 = (kt + 1) * BKT;
            const uint32_t ab = sA + (uint32_t)(((kt + 1) & 1) * A_STAGE_BYTES);
            const uint32_t bb = sB + (uint32_t)(((kt + 1) & 1) * B_STAGE_BYTES);
            const float* Ag = &A[(size_t)(bm + a_r) * K + k0 + a_k];
            cp16(ab + (uint32_t)((a_r * ASTR + a_k) * 4), Ag);
            cp16(ab + (uint32_t)((a_r * ASTR + a_k + 4) * 4), Ag + 4);
            const float* Bg = &B[(size_t)(k0 + b_r) * N + bn + b_n];
            cp16(bb + (uint32_t)((b_r * BSTR + b_n) * 4), Bg);
            cp16(bb + (uint32_t)((b_r * BSTR + b_n + 4) * 4), Bg + 4);
            asm volatile("cp.async.commit_group;\n" ::: "memory");
        }

        const float* as = As[kt & 1];
        const uint32_t* asu = reinterpret_cast<const uint32_t*>(as);
        const uint32_t* bsu = reinterpret_cast<const uint32_t*>(Bs[kt & 1]);

        #pragma unroll
        for (int kc = 0; kc < 2; ++kc) {
            const int kb = kc * 8 + tig;

            uint32_t af[4][4];
            #pragma unroll
            for (int mi = 0; mi < 4; ++mi) {
                const int o = (wm + mi * 16 + grp) * ASTR + kb;
                if (CVTA) {
                    af[mi][0] = cvt_tf32(as[o]);
                    af[mi][1] = cvt_tf32(as[o + 8 * ASTR]);
                    af[mi][2] = cvt_tf32(as[o + 4]);
                    af[mi][3] = cvt_tf32(as[o + 8 * ASTR + 4]);
                } else {
                    af[mi][0] = asu[o];
                    af[mi][1] = asu[o + 8 * ASTR];
                    af[mi][2] = asu[o + 4];
                    af[mi][3] = asu[o + 8 * ASTR + 4];
                }
            }
            uint32_t bf[4][2];
            #pragma unroll
            for (int ni = 0; ni < 4; ++ni) {
                const int o = kb * BSTR + wn + ni * 8 + grp;
                bf[ni][0] = bsu[o];
                bf[ni][1] = bsu[o + 4 * BSTR];
            }
            #pragma unroll
            for (int mi = 0; mi < 4; ++mi)
                #pragma unroll
                for (int ni = 0; ni < 4; ++ni)
                    mma8(acc[mi][ni], af[mi], bf[ni]);
        }
    }

    #pragma unroll
    for (int mi = 0; mi < 4; ++mi) {
        const int r0 = bm + wm + mi * 16 + grp;
        const int r1 = r0 + 8;
        float *row0, *row1;
        if (REMAP) {
            row0 = C + (size_t)((r0 & 63) * TT + (r0 >> 6)) * N;
            row1 = C + (size_t)((r1 & 63) * TT + (r1 >> 6)) * N;
        } else {
            row0 = C + (size_t)r0 * N;
            row1 = C + (size_t)r1 * N;
        }
        #pragma unroll
        for (int ni = 0; ni < 4; ++ni) {
            const int col = bn + wn + ni * 8 + tig * 2;
            float2 v0 = make_float2(acc[mi][ni][0], acc[mi][ni][1]);
            float2 v1 = make_float2(acc[mi][ni][2], acc[mi][ni][3]);
            if (BIAS) {
                const float bx = bias[col], by = bias[col + 1];
                v0.x += bx; v0.y += by; v1.x += bx; v1.y += by;
            }
            *reinterpret_cast<float2*>(&row0[col]) = v0;
            *reinterpret_cast<float2*>(&row1[col]) = v1;
        }
    }
}

// ---------------------------------------------------------------------------
// Small-tile TF32 GEMM for the lateral chain: 64x64 tile, BK=16, 128 threads
// (4 warps 2x2, warp tile 32x32). Grid = (N/64)x(M/64) = 16x20 = 320 CTAs
// for the lateral shape -> full chip coverage. Operands pre-rounded (no cvt).
// ---------------------------------------------------------------------------
#define SBM 64
#define SBN 64
#define SBSTR 72    // 64 + 8 (mod 32 == 8 -> conflict-free)
#define SA_STAGE_BYTES (SBM * ASTR * 4)
#define SB_STAGE_BYTES (BKT * SBSTR * 4)

__global__ __launch_bounds__(128, 4)
void gemm_tf32_64(const float* __restrict__ A, const float* __restrict__ B,
                  float* __restrict__ C, int M, int N, int K)
{
    __shared__ float As[2][SBM * ASTR];
    __shared__ float Bs[2][BKT * SBSTR];

    const int tid  = threadIdx.x;
    const int wid  = tid >> 5;
    const int lane = tid & 31;
    const int grp  = lane >> 2;
    const int tig  = lane & 3;
    const int wm   = (wid & 1) * 32;
    const int wn   = (wid >> 1) * 32;
    const int bm   = blockIdx.y * SBM;
    const int bn   = blockIdx.x * SBN;

    const uint32_t sA = (uint32_t)__cvta_generic_to_shared(&As[0][0]);
    const uint32_t sB = (uint32_t)__cvta_generic_to_shared(&Bs[0][0]);

    // A tile 64x16: 128 threads x 2 float4
    const int a_r = tid >> 1;           // 0..63
    const int a_k = (tid & 1) * 8;      // 0 or 8
    // B tile 16x64: 128 threads x 2 float4
    const int b_r = tid >> 3;           // 0..15
    const int b_n = (tid & 7) * 8;      // 0..56

    float acc[2][4][4];
    #pragma unroll
    for (int mi = 0; mi < 2; ++mi)
        #pragma unroll
        for (int ni = 0; ni < 4; ++ni)
            #pragma unroll
            for (int j = 0; j < 4; ++j) acc[mi][ni][j] = 0.0f;

    const int ktiles = K / BKT;

    {
        const float* Ag = &A[(size_t)(bm + a_r) * K + a_k];
        cp16(sA + (uint32_t)((a_r * ASTR + a_k) * 4), Ag);
        cp16(sA + (uint32_t)((a_r * ASTR + a_k + 4) * 4), Ag + 4);
        const float* Bg = &B[(size_t)b_r * N + bn + b_n];
        cp16(sB + (uint32_t)((b_r * SBSTR + b_n) * 4), Bg);
        cp16(sB + (uint32_t)((b_r * SBSTR + b_n + 4) * 4), Bg + 4);
        asm volatile("cp.async.commit_group;\n" ::: "memory");
    }

    for (int kt = 0; kt < ktiles; ++kt) {
        asm volatile("cp.async.wait_group 0;\n" ::: "memory");
        __syncthreads();

        if (kt + 1 < ktiles) {
            const int k0 = (kt + 1) * BKT;
            const uint32_t ab = sA + (uint32_t)(((kt + 1) & 1) * SA_STAGE_BYTES);
            const uint32_t bb = sB + (uint32_t)(((kt + 1) & 1) * SB_STAGE_BYTES);
            const float* Ag = &A[(size_t)(bm + a_r) * K + k0 + a_k];
            cp16(ab + (uint32_t)((a_r * ASTR + a_k) * 4), Ag);
            cp16(ab + (uint32_t)((a_r * ASTR + a_k + 4) * 4), Ag + 4);
            const float* Bg = &B[(size_t)(k0 + b_r) * N + bn + b_n];
            cp16(bb + (uint32_t)((b_r * SBSTR + b_n) * 4), Bg);
            cp16(bb + (uint32_t)((b_r * SBSTR + b_n + 4) * 4), Bg + 4);
            asm volatile("cp.async.commit_group;\n" ::: "memory");
        }

        const uint32_t* asu = reinterpret_cast<const uint32_t*>(As[kt & 1]);
        const uint32_t* bsu = reinterpret_cast<const uint32_t*>(Bs[kt & 1]);

        #pragma unroll
        for (int kc = 0; kc < 2; ++kc) {
            const int kb = kc * 8 + tig;

            uint32_t af[2][4];
            #pragma unroll
            for (int mi = 0; mi < 2; ++mi) {
                const int o = (wm + mi * 16 + grp) * ASTR + kb;
                af[mi][0] = asu[o];
                af[mi][1] = asu[o + 8 * ASTR];
                af[mi][2] = asu[o + 4];
                af[mi][3] = asu[o + 8 * ASTR + 4];
            }
            uint32_t bf[4][2];
            #pragma unroll
            for (int ni = 0; ni < 4; ++ni) {
                const int o = kb * SBSTR + wn + ni * 8 + grp;
                bf[ni][0] = bsu[o];
                bf[ni][1] = bsu[o + 4 * SBSTR];
            }
            #pragma unroll
            for (int mi = 0; mi < 2; ++mi)
                #pragma unroll
                for (int ni = 0; ni < 4; ++ni)
                    mma8(acc[mi][ni], af[mi], bf[ni]);
        }
    }

    #pragma unroll
    for (int mi = 0; mi < 2; ++mi) {
        const int r0 = bm + wm + mi * 16 + grp;
        float* row0 = C + (size_t)r0 * N;
        float* row1 = C + (size_t)(r0 + 8) * N;
        #pragma unroll
        for (int ni = 0; ni < 4; ++ni) {
            const int col = bn + wn + ni * 8 + tig * 2;
            *reinterpret_cast<float2*>(&row0[col]) = make_float2(acc[mi][ni][0], acc[mi][ni][1]);
            *reinterpret_cast<float2*>(&row1[col]) = make_float2(acc[mi][ni][2], acc[mi][ni][3]);
        }
    }
}

// ---------------------------------------------------------------------------
// W_out [DOUT, HID] -> g_WoutT [HID, DOUT], tf32-rounded on the way
// ---------------------------------------------------------------------------
__global__ void transpose_wout(const float* __restrict__ in, float* __restrict__ out)
{
    __shared__ float tile[32][33];
    const int bx = blockIdx.x * 32;   // HID coord
    const int by = blockIdx.y * 32;   // DOUT coord
    #pragma unroll
    for (int j = 0; j < 32; j += 8)
        tile[threadIdx.y + j][threadIdx.x] = __uint_as_float(cvt_tf32(
            in[(size_t)(by + threadIdx.y + j) * HID + bx + threadIdx.x]));
    __syncthreads();
    #pragma unroll
    for (int j = 0; j < 32; j += 8)
        out[(size_t)(bx + threadIdx.y + j) * DOUT + by + threadIdx.x] =
            tile[threadIdx.x][threadIdx.y + j];
}

// ---------------------------------------------------------------------------
// Elementwise recurrence over DELAYN=20 steps; 4 hidden units per thread.
// Stores firing tf32-rounded (so downstream GEMMs skip cvt). In-register
// recurrence stays exact.
// ---------------------------------------------------------------------------
__global__ __launch_bounds__(64)
void step_block(int k0step, int useLat,
                const float* __restrict__ thresh,
                const float* __restrict__ tkm,
                const float* __restrict__ tak,
                const float* __restrict__ amp,
                const float* __restrict__ tar)
{
    const int idx = blockIdx.x * 64 + threadIdx.x;
    const int h = (idx & 255) * 4;
    const int b = idx >> 8;
    const int base = b * HID + h;

    float th[4], rk[4], omk[4], dk0[4], dk1[4], odk0[4], odk1[4];
    float am0[4], am1[4], rr0[4], rr1[4];
    {
        float4 t = *reinterpret_cast<const float4*>(&thresh[h]);
        th[0] = t.x; th[1] = t.y; th[2] = t.z; th[3] = t.w;
        float4 m = *reinterpret_cast<const float4*>(&tkm[h]);
        float mm[4] = {m.x, m.y, m.z, m.w};
        float4 k0v = *reinterpret_cast<const float4*>(&tak[h]);
        float4 k1v = *reinterpret_cast<const float4*>(&tak[HID + h]);
        float kk0[4] = {k0v.x, k0v.y, k0v.z, k0v.w};
        float kk1[4] = {k1v.x, k1v.y, k1v.z, k1v.w};
        float4 a0v = *reinterpret_cast<const float4*>(&amp[h]);
        float4 a1v = *reinterpret_cast<const float4*>(&amp[HID + h]);
        am0[0] = a0v.x; am0[1] = a0v.y; am0[2] = a0v.z; am0[3] = a0v.w;
        am1[0] = a1v.x; am1[1] = a1v.y; am1[2] = a1v.z; am1[3] = a1v.w;
        float4 r0v = *reinterpret_cast<const float4*>(&tar[h]);
        float4 r1v = *reinterpret_cast<const float4*>(&tar[HID + h]);
        float rv0[4] = {r0v.x, r0v.y, r0v.z, r0v.w};
        float rv1[4] = {r1v.x, r1v.y, r1v.z, r1v.w};
        #pragma unroll
        for (int j = 0; j < 4; ++j) {
            const float km = 1.0f / (1.0f + expf(-mm[j]));
            rk[j]  = 0.1f * km;
            omk[j] = 1.0f - km;
            dk0[j] = 1.0f / (1.0f + expf(-kk0[j]));
            dk1[j] = 1.0f / (1.0f + expf(-kk1[j]));
            odk0[j] = 1.0f - dk0[j];
            odk1[j] = 1.0f - dk1[j];
            rr0[j] = 1.0f - 2.0f / (1.0f + expf(-rv0[j]));
            rr1[j] = 1.0f - 2.0f / (1.0f + expf(-rv1[j]));
        }
    }

    float v[4], a0[4], a1[4], f[4];
    if (k0step == 0) {
        #pragma unroll
        for (int j = 0; j < 4; ++j) { v[j] = 0.f; a0[j] = 0.f; a1[j] = 0.f; f[j] = 0.f; }
    } else {
        float4 vv = *reinterpret_cast<const float4*>(&g_volt[base]);
        float4 aa0 = *reinterpret_cast<const float4*>(&g_asc[base]);
        float4 aa1 = *reinterpret_cast<const float4*>(&g_asc[NB * HID + base]);
        float4 ff = *reinterpret_cast<const float4*>(&g_fir[(size_t)(k0step - 1) * NB * HID + base]);
        v[0] = vv.x; v[1] = vv.y; v[2] = vv.z; v[3] = vv.w;
        a0[0] = aa0.x; a0[1] = aa0.y; a0[2] = aa0.z; a0[3] = aa0.w;
        a1[0] = aa1.x; a1[1] = aa1.y; a1[2] = aa1.z; a1[3] = aa1.w;
        f[0] = ff.x; f[1] = ff.y; f[2] = ff.z; f[3] = ff.w;
    }

    #pragma unroll
    for (int s = 0; s < DELAYN; ++s) {
        const int t = k0step + s;
        float4 syn = *reinterpret_cast<const float4*>(&g_xp[((size_t)b * TT + t) * HID + h]);
        float sy[4] = {syn.x, syn.y, syn.z, syn.w};
        if (useLat) {
            float4 l = *reinterpret_cast<const float4*>(&g_lat[((size_t)s * NB + b) * HID + h]);
            sy[0] += l.x; sy[1] += l.y; sy[2] += l.z; sy[3] += l.w;
        }
        #pragma unroll
        for (int j = 0; j < 4; ++j) {
            a0[j] = (am0[j] + rr0[j] * a0[j]) * f[j] * dk0[j] + odk0[j] * a0[j];
            a1[j] = (am1[j] + rr1[j] * a1[j]) * f[j] * dk1[j] + odk1[j] * a1[j];
            v[j]  = rk[j] * (sy[j] + a0[j] + a1[j]) + omk[j] * v[j];
            f[j]  = __fdividef(1.0f, 1.0f + __expf(-(v[j] - th[j])));
        }
        float4 o;
        o.x = __uint_as_float(cvt_tf32(f[0]));
        o.y = __uint_as_float(cvt_tf32(f[1]));
        o.z = __uint_as_float(cvt_tf32(f[2]));
        o.w = __uint_as_float(cvt_tf32(f[3]));
        *reinterpret_cast<float4*>(&g_fir[((size_t)t * NB + b) * HID + h]) = o;
    }

    *reinterpret_cast<float4*>(&g_volt[base]) = make_float4(v[0], v[1], v[2], v[3]);
    *reinterpret_cast<float4*>(&g_asc[base]) = make_float4(a0[0], a0[1], a0[2], a0[3]);
    *reinterpret_cast<float4*>(&g_asc[NB * HID + base]) = make_float4(a1[0], a1[1], a1[2], a1[3]);
}

extern "C" void kernel_launch(void* const* d_in, const int* in_sizes, int n_in,
                              void* d_out, int out_size)
{
    const float* x      = (const float*)d_in[0];
    const float* W_in   = (const float*)d_in[1];
    const float* W_lat  = (const float*)d_in[2];
    const float* thresh = (const float*)d_in[3];
    const float* tkm    = (const float*)d_in[4];
    const float* tak    = (const float*)d_in[5];
    const float* amp    = (const float*)d_in[6];
    const float* tar    = (const float*)d_in[7];
    const float* W_out  = (const float*)d_in[8];
    const float* b_out  = (const float*)d_in[9];
    float* out = (float*)d_out;

    float *xp, *fir, *lat, *woutT, *wlat32, *win32;
    cudaGetSymbolAddress((void**)&xp,  g_xp);
    cudaGetSymbolAddress((void**)&fir, g_fir);
    cudaGetSymbolAddress((void**)&lat, g_lat);
    cudaGetSymbolAddress((void**)&woutT, g_WoutT);
    cudaGetSymbolAddress((void**)&wlat32, g_Wlat32);
    cudaGetSymbolAddress((void**)&win32, g_Win32);

    // 0) Pre-round weights to tf32 (removes cvt from GEMM hot loops)
    round_tf32_kernel<<<(HID * HID / 4 + 255) / 256, 256>>>(W_lat, wlat32, HID * HID / 4);
    round_tf32_kernel<<<(DIN * HID / 4 + 255) / 256, 256>>>(W_in, win32, DIN * HID / 4);
    transpose_wout<<<dim3(HID / 32, DOUT / 32), dim3(32, 8)>>>(W_out, woutT);

    // 1) Input projection: [12800,512] @ [512,1024] -> g_xp  (cvt on A only)
    gemm_tf32<0, 0, 1><<<dim3(HID / BN, (NB * TT) / BM), 256>>>(
        x, win32, xp, nullptr, NB * TT, HID, DIN);

    // 2) Ten blocks of 20 steps: lateral GEMM (64x64 tiles, 320 CTAs) + recurrence
    for (int k = 0; k < NBLK; ++k) {
        if (k > 0) {
            gemm_tf32_64<<<dim3(HID / SBN, (DELAYN * NB) / SBM), 128>>>(
                fir + (size_t)(k - 1) * DELAYN * NB * HID, wlat32, lat,
                DELAYN * NB, HID, HID);
        }
        step_block<<<(NB * HID / 4) / 64, 64>>>(k * DELAYN, k > 0, thresh, tkm, tak, amp, tar);
    }

    // 3) Readout: [12800,1024] @ [1024,512] + bias, remapped to [B,T,OUT]
    gemm_tf32<1, 1, 0><<<dim3(DOUT / BN, (NB * TT) / BM), 256>>>(
        fir, woutT, out, b_out, NB * TT, DOUT, HID);
}

// round 13
// speedup vs baseline: 4.8099x; 1.8301x over previous
#include <cuda_runtime.h>
#include <cuda_fp16.h>
#include <math.h>
#include <stdint.h>

// Problem constants
#define NB   64
#define TT   200
#define DIN  512
#define HID  1024
#define DOUT 512
#define DELAYN 20
#define NBLK 10

// Persistent scratch (device globals — no allocation allowed)
__device__ __align__(16) float  g_xp   [NB * TT * HID];     // x @ W_in, [B,T,H] fp32
__device__ __align__(16) __half g_fir16[TT * NB * HID];     // firing fp16, [T,B,H]
__device__ __align__(16) float  g_lat  [DELAYN * NB * HID]; // lateral contrib fp32, [s,B,H]
__device__ __align__(16) float  g_volt [NB * HID];
__device__ __align__(16) float  g_asc  [2 * NB * HID];
__device__ __align__(16) __half g_x16  [NB * TT * DIN];     // x as fp16 [B*T, IN]
__device__ __align__(16) __half g_Win16[HID * DIN];         // W_in^T  [HID, DIN]  ([N,K])
__device__ __align__(16) __half g_Wlat16[HID * HID];        // W_lat^T [HID, HID]  ([N,K])
__device__ __align__(16) __half g_Wout16[DOUT * HID];       // W_out   [DOUT, HID] ([N,K])

// ---------------------------------------------------------------------------
// mma / ldmatrix / cp.async helpers (legacy tensor path — sm_103 ptxas-safe)
// ---------------------------------------------------------------------------
__device__ __forceinline__ void cp16(uint32_t dst, const void* src) {
    asm volatile("cp.async.cg.shared.global [%0], [%1], 16;\n" :: "r"(dst), "l"(src));
}
__device__ __forceinline__ void ldm_x4(uint32_t* r, uint32_t addr) {
    asm volatile("ldmatrix.sync.aligned.m8n8.x4.shared.b16 {%0,%1,%2,%3}, [%4];"
        : "=r"(r[0]), "=r"(r[1]), "=r"(r[2]), "=r"(r[3]) : "r"(addr));
}
__device__ __forceinline__ void ldm_x2(uint32_t* r, uint32_t addr) {
    asm volatile("ldmatrix.sync.aligned.m8n8.x2.shared.b16 {%0,%1}, [%2];"
        : "=r"(r[0]), "=r"(r[1]) : "r"(addr));
}
__device__ __forceinline__ void mma16(float* c, const uint32_t* a, const uint32_t* b) {
    asm volatile(
        "mma.sync.aligned.m16n8k16.row.col.f32.f16.f16.f32 "
        "{%0,%1,%2,%3}, {%4,%5,%6,%7}, {%8,%9}, {%0,%1,%2,%3};\n"
        : "+f"(c[0]), "+f"(c[1]), "+f"(c[2]), "+f"(c[3])
        : "r"(a[0]), "r"(a[1]), "r"(a[2]), "r"(a[3]), "r"(b[0]), "r"(b[1]));
}

// ---------------------------------------------------------------------------
// FP16 tensor GEMM (big): C[M,N]f32 = A[M,K]f16 * B[N,K]f16^T (+bias, remap)
// 128x128 tile, BK=32, 256 threads (8 warps 2m x 4n, warp tile 64x32),
// double-buffered cp.async, ldmatrix fragment loads.
// Rows padded to 40 halves (80B) -> every ldmatrix phase covers all 32 banks.
// Requires M%128==0, N%128==0, K%32==0.
// ---------------------------------------------------------------------------
#define HSTR 40
#define BSTAGE (128 * HSTR * 2)   // bytes per stage (A or B tile)

template<int REMAP, int BIAS>
__global__ __launch_bounds__(256, 2)
void gemm_f16(const __half* __restrict__ A, const __half* __restrict__ B,
              float* __restrict__ C, const float* __restrict__ bias,
              int M, int N, int K)
{
    __shared__ __half As[2][128 * HSTR];
    __shared__ __half Bs[2][128 * HSTR];

    const int tid  = threadIdx.x;
    const int wid  = tid >> 5;
    const int lane = tid & 31;
    const int grp  = lane >> 2;
    const int tig  = lane & 3;
    const int wm   = (wid & 1) * 64;
    const int wn   = (wid >> 1) * 32;
    const int bm   = blockIdx.y * 128;
    const int bn   = blockIdx.x * 128;

    const uint32_t sA = (uint32_t)__cvta_generic_to_shared(&As[0][0]);
    const uint32_t sB = (uint32_t)__cvta_generic_to_shared(&Bs[0][0]);

    float acc[4][4][4];
    #pragma unroll
    for (int mi = 0; mi < 4; ++mi)
        #pragma unroll
        for (int ni = 0; ni < 4; ++ni)
            #pragma unroll
            for (int j = 0; j < 4; ++j) acc[mi][ni][j] = 0.0f;

    const int nkb = K >> 5;
    const int r0 = tid >> 2, c0 = (tid & 3) * 8;          // chunk 0
    const int r1 = (tid + 256) >> 2;                      // chunk 1 (same c)

    auto load_stage = [&](int s, int kb) {
        const __half* Ag = A + (size_t)bm * K + kb * 32;
        const __half* Bg = B + (size_t)bn * K + kb * 32;
        cp16(sA + s * BSTAGE + (r0 * HSTR + c0) * 2, Ag + (size_t)r0 * K + c0);
        cp16(sA + s * BSTAGE + (r1 * HSTR + c0) * 2, Ag + (size_t)r1 * K + c0);
        cp16(sB + s * BSTAGE + (r0 * HSTR + c0) * 2, Bg + (size_t)r0 * K + c0);
        cp16(sB + s * BSTAGE + (r1 * HSTR + c0) * 2, Bg + (size_t)r1 * K + c0);
        asm volatile("cp.async.commit_group;\n" ::: "memory");
    };

    load_stage(0, 0);

    // per-lane ldmatrix row/k offsets
    const int a_row = wm + (lane & 7) + ((lane >> 3) & 1) * 8;  // + matrix2/3 k-offset below
    const int a_koff = (lane >> 4) * 8;
    const int b_row = wn + (lane & 7);
    const int b_koff = ((lane >> 3) & 1) * 8;

    for (int kt = 0; kt < nkb; ++kt) {
        const int s = kt & 1;
        asm volatile("cp.async.wait_group 0;\n" ::: "memory");
        __syncthreads();
        if (kt + 1 < nkb) load_stage(s ^ 1, kt + 1);

        #pragma unroll
        for (int kc = 0; kc < 2; ++kc) {
            uint32_t af[4][4], bf[4][2];
            const int ak = kc * 16 + a_koff;
            const int bk = kc * 16 + b_koff;
            #pragma unroll
            for (int mi = 0; mi < 4; ++mi)
                ldm_x4(af[mi], sA + s * BSTAGE + ((a_row + mi * 16) * HSTR + ak) * 2);
            #pragma unroll
            for (int ni = 0; ni < 4; ++ni)
                ldm_x2(bf[ni], sB + s * BSTAGE + ((b_row + ni * 8) * HSTR + bk) * 2);
            #pragma unroll
            for (int mi = 0; mi < 4; ++mi)
                #pragma unroll
                for (int ni = 0; ni < 4; ++ni)
                    mma16(acc[mi][ni], af[mi], bf[ni]);
        }
        __syncthreads();
    }

    // epilogue (c frag: rows g, g+8; cols 2*tig, 2*tig+1)
    #pragma unroll
    for (int mi = 0; mi < 4; ++mi) {
        const int rr0 = bm + wm + mi * 16 + grp;
        const int rr1 = rr0 + 8;
        float *row0, *row1;
        if (REMAP) {
            row0 = C + ((size_t)(rr0 & 63) * TT + (rr0 >> 6)) * N;
            row1 = C + ((size_t)(rr1 & 63) * TT + (rr1 >> 6)) * N;
        } else {
            row0 = C + (size_t)rr0 * N;
            row1 = C + (size_t)rr1 * N;
        }
        #pragma unroll
        for (int ni = 0; ni < 4; ++ni) {
            const int col = bn + wn + ni * 8 + tig * 2;
            float2 v0 = make_float2(acc[mi][ni][0], acc[mi][ni][1]);
            float2 v1 = make_float2(acc[mi][ni][2], acc[mi][ni][3]);
            if (BIAS) {
                const float bx = bias[col], by = bias[col + 1];
                v0.x += bx; v0.y += by; v1.x += bx; v1.y += by;
            }
            *reinterpret_cast<float2*>(&row0[col]) = v0;
            *reinterpret_cast<float2*>(&row1[col]) = v1;
        }
    }
}

// ---------------------------------------------------------------------------
// FP16 tensor GEMM (small, lateral): 64x64 tile, BK=32, 128 threads
// (4 warps 2x2, warp tile 32x32). Grid 16x20 = 320 CTAs -> full chip.
// ---------------------------------------------------------------------------
#define SSTAGE (64 * HSTR * 2)

__global__ __launch_bounds__(128, 4)
void gemm_f16_64(const __half* __restrict__ A, const __half* __restrict__ B,
                 float* __restrict__ C, int M, int N, int K)
{
    __shared__ __half As[2][64 * HSTR];
    __shared__ __half Bs[2][64 * HSTR];

    const int tid  = threadIdx.x;
    const int wid  = tid >> 5;
    const int lane = tid & 31;
    const int grp  = lane >> 2;
    const int tig  = lane & 3;
    const int wm   = (wid & 1) * 32;
    const int wn   = (wid >> 1) * 32;
    const int bm   = blockIdx.y * 64;
    const int bn   = blockIdx.x * 64;

    const uint32_t sA = (uint32_t)__cvta_generic_to_shared(&As[0][0]);
    const uint32_t sB = (uint32_t)__cvta_generic_to_shared(&Bs[0][0]);

    float acc[2][4][4];
    #pragma unroll
    for (int mi = 0; mi < 2; ++mi)
        #pragma unroll
        for (int ni = 0; ni < 4; ++ni)
            #pragma unroll
            for (int j = 0; j < 4; ++j) acc[mi][ni][j] = 0.0f;

    const int nkb = K >> 5;
    const int r0 = tid >> 2, c0 = (tid & 3) * 8;
    const int r1 = (tid + 128) >> 2;

    auto load_stage = [&](int s, int kb) {
        const __half* Ag = A + (size_t)bm * K + kb * 32;
        const __half* Bg = B + (size_t)bn * K + kb * 32;
        cp16(sA + s * SSTAGE + (r0 * HSTR + c0) * 2, Ag + (size_t)r0 * K + c0);
        cp16(sA + s * SSTAGE + (r1 * HSTR + c0) * 2, Ag + (size_t)r1 * K + c0);
        cp16(sB + s * SSTAGE + (r0 * HSTR + c0) * 2, Bg + (size_t)r0 * K + c0);
        cp16(sB + s * SSTAGE + (r1 * HSTR + c0) * 2, Bg + (size_t)r1 * K + c0);
        asm volatile("cp.async.commit_group;\n" ::: "memory");
    };

    load_stage(0, 0);

    const int a_row = wm + (lane & 7) + ((lane >> 3) & 1) * 8;
    const int a_koff = (lane >> 4) * 8;
    const int b_row = wn + (lane & 7);
    const int b_koff = ((lane >> 3) & 1) * 8;

    for (int kt = 0; kt < nkb; ++kt) {
        const int s = kt & 1;
        asm volatile("cp.async.wait_group 0;\n" ::: "memory");
        __syncthreads();
        if (kt + 1 < nkb) load_stage(s ^ 1, kt + 1);

        #pragma unroll
        for (int kc = 0; kc < 2; ++kc) {
            uint32_t af[2][4], bf[4][2];
            const int ak = kc * 16 + a_koff;
            const int bk = kc * 16 + b_koff;
            #pragma unroll
            for (int mi = 0; mi < 2; ++mi)
                ldm_x4(af[mi], sA + s * SSTAGE + ((a_row + mi * 16) * HSTR + ak) * 2);
            #pragma unroll
            for (int ni = 0; ni < 4; ++ni)
                ldm_x2(bf[ni], sB + s * SSTAGE + ((b_row + ni * 8) * HSTR + bk) * 2);
            #pragma unroll
            for (int mi = 0; mi < 2; ++mi)
                #pragma unroll
                for (int ni = 0; ni < 4; ++ni)
                    mma16(acc[mi][ni], af[mi], bf[ni]);
        }
        __syncthreads();
    }

    #pragma unroll
    for (int mi = 0; mi < 2; ++mi) {
        const int rr0 = bm + wm + mi * 16 + grp;
        float* row0 = C + (size_t)rr0 * N;
        float* row1 = C + (size_t)(rr0 + 8) * N;
        #pragma unroll
        for (int ni = 0; ni < 4; ++ni) {
            const int col = bn + wn + ni * 8 + tig * 2;
            *reinterpret_cast<float2*>(&row0[col]) = make_float2(acc[mi][ni][0], acc[mi][ni][1]);
            *reinterpret_cast<float2*>(&row1[col]) = make_float2(acc[mi][ni][2], acc[mi][ni][3]);
        }
    }
}

// ---------------------------------------------------------------------------
// fp32 -> fp16 elementwise (float4 in, 4 halves out)
// ---------------------------------------------------------------------------
__global__ void f32_to_f16(const float* __restrict__ in, __half* __restrict__ out, int n4)
{
    int i = blockIdx.x * blockDim.x + threadIdx.x;
    if (i >= n4) return;
    float4 v = reinterpret_cast<const float4*>(in)[i];
    __half2 lo = __floats2half2_rn(v.x, v.y);
    __half2 hi = __floats2half2_rn(v.z, v.w);
    uint2 o;
    o.x = *reinterpret_cast<uint32_t*>(&lo);
    o.y = *reinterpret_cast<uint32_t*>(&hi);
    reinterpret_cast<uint2*>(out)[i] = o;
}

// ---------------------------------------------------------------------------
// Transpose f32 [R,C] -> f16 [C,R]
// ---------------------------------------------------------------------------
__global__ void transpose_f16(const float* __restrict__ in, __half* __restrict__ out,
                              int R, int C)
{
    __shared__ float tile[32][33];
    const int bx = blockIdx.x * 32;   // C coord
    const int by = blockIdx.y * 32;   // R coord
    #pragma unroll
    for (int j = 0; j < 32; j += 8)
        tile[threadIdx.y + j][threadIdx.x] =
            in[(size_t)(by + threadIdx.y + j) * C + bx + threadIdx.x];
    __syncthreads();
    #pragma unroll
    for (int j = 0; j < 32; j += 8)
        out[(size_t)(bx + threadIdx.y + j) * R + by + threadIdx.x] =
            __float2half(tile[threadIdx.x][threadIdx.y + j]);
}

// ---------------------------------------------------------------------------
// Elementwise recurrence over DELAYN=20 steps; 4 hidden units per thread.
// Firing written as fp16 (feeds lateral + readout GEMMs directly).
// ---------------------------------------------------------------------------
__global__ __launch_bounds__(64)
void step_block(int k0step, int useLat,
                const float* __restrict__ thresh,
                const float* __restrict__ tkm,
                const float* __restrict__ tak,
                const float* __restrict__ amp,
                const float* __restrict__ tar)
{
    const int idx = blockIdx.x * 64 + threadIdx.x;
    const int h = (idx & 255) * 4;
    const int b = idx >> 8;
    const int base = b * HID + h;

    float th[4], rk[4], omk[4], dk0[4], dk1[4], odk0[4], odk1[4];
    float am0[4], am1[4], rr0[4], rr1[4];
    {
        float4 t = *reinterpret_cast<const float4*>(&thresh[h]);
        th[0] = t.x; th[1] = t.y; th[2] = t.z; th[3] = t.w;
        float4 m = *reinterpret_cast<const float4*>(&tkm[h]);
        float mm[4] = {m.x, m.y, m.z, m.w};
        float4 k0v = *reinterpret_cast<const float4*>(&tak[h]);
        float4 k1v = *reinterpret_cast<const float4*>(&tak[HID + h]);
        float kk0[4] = {k0v.x, k0v.y, k0v.z, k0v.w};
        float kk1[4] = {k1v.x, k1v.y, k1v.z, k1v.w};
        float4 a0v = *reinterpret_cast<const float4*>(&amp[h]);
        float4 a1v = *reinterpret_cast<const float4*>(&amp[HID + h]);
        am0[0] = a0v.x; am0[1] = a0v.y; am0[2] = a0v.z; am0[3] = a0v.w;
        am1[0] = a1v.x; am1[1] = a1v.y; am1[2] = a1v.z; am1[3] = a1v.w;
        float4 r0v = *reinterpret_cast<const float4*>(&tar[h]);
        float4 r1v = *reinterpret_cast<const float4*>(&tar[HID + h]);
        float rv0[4] = {r0v.x, r0v.y, r0v.z, r0v.w};
        float rv1[4] = {r1v.x, r1v.y, r1v.z, r1v.w};
        #pragma unroll
        for (int j = 0; j < 4; ++j) {
            const float km = 1.0f / (1.0f + expf(-mm[j]));
            rk[j]  = 0.1f * km;
            omk[j] = 1.0f - km;
            dk0[j] = 1.0f / (1.0f + expf(-kk0[j]));
            dk1[j] = 1.0f / (1.0f + expf(-kk1[j]));
            odk0[j] = 1.0f - dk0[j];
            odk1[j] = 1.0f - dk1[j];
            rr0[j] = 1.0f - 2.0f / (1.0f + expf(-rv0[j]));
            rr1[j] = 1.0f - 2.0f / (1.0f + expf(-rv1[j]));
        }
    }

    float v[4], a0[4], a1[4], f[4];
    if (k0step == 0) {
        #pragma unroll
        for (int j = 0; j < 4; ++j) { v[j] = 0.f; a0[j] = 0.f; a1[j] = 0.f; f[j] = 0.f; }
    } else {
        float4 vv  = *reinterpret_cast<const float4*>(&g_volt[base]);
        float4 aa0 = *reinterpret_cast<const float4*>(&g_asc[base]);
        float4 aa1 = *reinterpret_cast<const float4*>(&g_asc[NB * HID + base]);
        uint2 fu = *reinterpret_cast<const uint2*>(&g_fir16[(size_t)(k0step - 1) * NB * HID + base]);
        __half2 f01 = *reinterpret_cast<__half2*>(&fu.x);
        __half2 f23 = *reinterpret_cast<__half2*>(&fu.y);
        v[0] = vv.x; v[1] = vv.y; v[2] = vv.z; v[3] = vv.w;
        a0[0] = aa0.x; a0[1] = aa0.y; a0[2] = aa0.z; a0[3] = aa0.w;
        a1[0] = aa1.x; a1[1] = aa1.y; a1[2] = aa1.z; a1[3] = aa1.w;
        f[0] = __half2float(f01.x); f[1] = __half2float(f01.y);
        f[2] = __half2float(f23.x); f[3] = __half2float(f23.y);
    }

    #pragma unroll
    for (int s = 0; s < DELAYN; ++s) {
        const int t = k0step + s;
        float4 syn = *reinterpret_cast<const float4*>(&g_xp[((size_t)b * TT + t) * HID + h]);
        float sy[4] = {syn.x, syn.y, syn.z, syn.w};
        if (useLat) {
            float4 l = *reinterpret_cast<const float4*>(&g_lat[((size_t)s * NB + b) * HID + h]);
            sy[0] += l.x; sy[1] += l.y; sy[2] += l.z; sy[3] += l.w;
        }
        #pragma unroll
        for (int j = 0; j < 4; ++j) {
            a0[j] = (am0[j] + rr0[j] * a0[j]) * f[j] * dk0[j] + odk0[j] * a0[j];
            a1[j] = (am1[j] + rr1[j] * a1[j]) * f[j] * dk1[j] + odk1[j] * a1[j];
            v[j]  = rk[j] * (sy[j] + a0[j] + a1[j]) + omk[j] * v[j];
            f[j]  = __fdividef(1.0f, 1.0f + __expf(-(v[j] - th[j])));
        }
        __half2 lo = __floats2half2_rn(f[0], f[1]);
        __half2 hi = __floats2half2_rn(f[2], f[3]);
        uint2 o;
        o.x = *reinterpret_cast<uint32_t*>(&lo);
        o.y = *reinterpret_cast<uint32_t*>(&hi);
        *reinterpret_cast<uint2*>(&g_fir16[((size_t)t * NB + b) * HID + h]) = o;
    }

    *reinterpret_cast<float4*>(&g_volt[base]) = make_float4(v[0], v[1], v[2], v[3]);
    *reinterpret_cast<float4*>(&g_asc[base]) = make_float4(a0[0], a0[1], a0[2], a0[3]);
    *reinterpret_cast<float4*>(&g_asc[NB * HID + base]) = make_float4(a1[0], a1[1], a1[2], a1[3]);
}

extern "C" void kernel_launch(void* const* d_in, const int* in_sizes, int n_in,
                              void* d_out, int out_size)
{
    const float* x      = (const float*)d_in[0];
    const float* W_in   = (const float*)d_in[1];
    const float* W_lat  = (const float*)d_in[2];
    const float* thresh = (const float*)d_in[3];
    const float* tkm    = (const float*)d_in[4];
    const float* tak    = (const float*)d_in[5];
    const float* amp    = (const float*)d_in[6];
    const float* tar    = (const float*)d_in[7];
    const float* W_out  = (const float*)d_in[8];
    const float* b_out  = (const float*)d_in[9];
    float* out = (float*)d_out;

    float *xp, *lat;
    __half *x16, *fir16, *win16, *wlat16, *wout16;
    cudaGetSymbolAddress((void**)&xp,     g_xp);
    cudaGetSymbolAddress((void**)&lat,    g_lat);
    cudaGetSymbolAddress((void**)&x16,    g_x16);
    cudaGetSymbolAddress((void**)&fir16,  g_fir16);
    cudaGetSymbolAddress((void**)&win16,  g_Win16);
    cudaGetSymbolAddress((void**)&wlat16, g_Wlat16);
    cudaGetSymbolAddress((void**)&wout16, g_Wout16);

    // 0) fp16 operand prep
    f32_to_f16<<<(NB * TT * DIN / 4 + 255) / 256, 256>>>(x, x16, NB * TT * DIN / 4);
    transpose_f16<<<dim3(HID / 32, DIN / 32), dim3(32, 8)>>>(W_in, win16, DIN, HID);
    transpose_f16<<<dim3(HID / 32, HID / 32), dim3(32, 8)>>>(W_lat, wlat16, HID, HID);
    f32_to_f16<<<(DOUT * HID / 4 + 255) / 256, 256>>>(W_out, wout16, DOUT * HID / 4);

    // 1) Input projection: [12800,512] @ [1024,512]^T -> g_xp
    gemm_f16<0, 0><<<dim3(HID / 128, (NB * TT) / 128), 256>>>(
        x16, win16, xp, nullptr, NB * TT, HID, DIN);

    // 2) Ten blocks of 20 steps: lateral GEMM (64x64 tiles, 320 CTAs) + recurrence
    for (int k = 0; k < NBLK; ++k) {
        if (k > 0) {
            gemm_f16_64<<<dim3(HID / 64, (DELAYN * NB) / 64), 128>>>(
                fir16 + (size_t)(k - 1) * DELAYN * NB * HID, wlat16, lat,
                DELAYN * NB, HID, HID);
        }
        step_block<<<(NB * HID / 4) / 64, 64>>>(k * DELAYN, k > 0, thresh, tkm, tak, amp, tar);
    }

    // 3) Readout: [12800,1024] @ [512,1024]^T + bias, remapped to [B,T,OUT]
    gemm_f16<1, 1><<<dim3(DOUT / 128, (NB * TT) / 128), 256>>>(
        fir16, wout16, out, b_out, NB * TT, DOUT, HID);
}